// round 5
// baseline (speedup 1.0000x reference)
#include <cuda_runtime.h>
#include <math.h>

#define N_NODES 65536
#define DIM     128
#define GR      128
#define NE      262144
#define GSTEPS  6

// packed fp32x2 FMA: d = a*b + d (elementwise on 2 packed floats)
#define FMA2(d, a, b) asm("fma.rn.f32x2 %0, %1, %2, %0;" : "+l"(d) : "l"(a), "l"(b))

union PackF2 { unsigned long long u; float2 f; };

// ---------------- scratch (static device allocations; no cudaMalloc) ----------------
__device__ float g_H  [N_NODES * DIM];
__device__ float g_M  [N_NODES * DIM];
__device__ float g_AGG[N_NODES * DIM];
__device__ float g_GX [N_NODES * 384];
__device__ float g_GH [N_NODES * 384];
__device__ float g_WT [GSTEPS * DIM * DIM];
__device__ float g_CAT[256 * N_NODES];
__device__ float g_T1 [128 * GR * 510];
__device__ float g_P1 [128 * GR * 254];
__device__ float g_T2 [128 * GR * 254];
__device__ float g_P2 [128 * GR * 127];
__device__ float g_U1 [256 * GR * 510];
__device__ float g_Q1 [256 * GR * 254];
__device__ float g_U2 [256 * GR * 254];
__device__ float g_Q2 [256 * GR * 127];
__device__ float g_MEAN[256];
__device__ float g_RSTD[256];

// ---------------- packed 128x128x8 fp32 SGEMM:  C[M,N] = A[M,K]*B[N,K]^T (+bias per col) --------
// A values stored DUPLICATED in shared ((a,a) pairs) so broadcast operand loads pre-packed.
__global__ __launch_bounds__(256) void gemm_nt(
    const float* __restrict__ A, const float* __restrict__ B,
    const float* __restrict__ bias, float* __restrict__ C,
    int Ncols, int K)
{
    __shared__ float AsD[2][8][256];   // duplicated: AsD[k][2r]=AsD[k][2r+1]=A[row r]
    __shared__ float Bs [2][8][128];
    const int tid  = threadIdx.x;
    const int lrow = tid >> 1;
    const int lcol = (tid & 1) << 2;
    const int tx   = tid & 15;
    const int ty   = tid >> 4;

    const float* Ab = A + (size_t)blockIdx.x * 128 * K + (size_t)lrow * K + lcol;
    const float* Bb = B + (size_t)blockIdx.y * 128 * K + (size_t)lrow * K + lcol;

    unsigned long long acc[8][4];
#pragma unroll
    for (int i = 0; i < 8; i++)
#pragma unroll
        for (int j = 0; j < 4; j++) acc[i][j] = 0ull;

    {
        float4 av = *(const float4*)Ab;
        float4 bv = *(const float4*)Bb;
        *(float2*)&AsD[0][lcol + 0][2 * lrow] = make_float2(av.x, av.x);
        *(float2*)&AsD[0][lcol + 1][2 * lrow] = make_float2(av.y, av.y);
        *(float2*)&AsD[0][lcol + 2][2 * lrow] = make_float2(av.z, av.z);
        *(float2*)&AsD[0][lcol + 3][2 * lrow] = make_float2(av.w, av.w);
        Bs[0][lcol + 0][lrow] = bv.x; Bs[0][lcol + 1][lrow] = bv.y;
        Bs[0][lcol + 2][lrow] = bv.z; Bs[0][lcol + 3][lrow] = bv.w;
    }
    __syncthreads();

    const int nk = K >> 3;
    int buf = 0;
    for (int kt = 0; kt < nk; kt++) {
        float4 avn, bvn;
        const bool has = (kt + 1) < nk;
        if (has) {
            avn = *(const float4*)(Ab + (kt + 1) * 8);
            bvn = *(const float4*)(Bb + (kt + 1) * 8);
        }
#pragma unroll
        for (int kk = 0; kk < 8; kk++) {
            const ulonglong2* ap = (const ulonglong2*)&AsD[buf][kk][ty * 16];
            const ulonglong2* bp = (const ulonglong2*)&Bs[buf][kk][tx * 8];
            ulonglong2 a01 = ap[0], a23 = ap[1], a45 = ap[2], a67 = ap[3];
            ulonglong2 b01 = bp[0], b23 = bp[1];
            unsigned long long a[8] = {a01.x, a01.y, a23.x, a23.y, a45.x, a45.y, a67.x, a67.y};
            unsigned long long bb[4] = {b01.x, b01.y, b23.x, b23.y};
#pragma unroll
            for (int i = 0; i < 8; i++)
#pragma unroll
                for (int j = 0; j < 4; j++) FMA2(acc[i][j], a[i], bb[j]);
        }
        if (has) {
            const int nb = buf ^ 1;
            *(float2*)&AsD[nb][lcol + 0][2 * lrow] = make_float2(avn.x, avn.x);
            *(float2*)&AsD[nb][lcol + 1][2 * lrow] = make_float2(avn.y, avn.y);
            *(float2*)&AsD[nb][lcol + 2][2 * lrow] = make_float2(avn.z, avn.z);
            *(float2*)&AsD[nb][lcol + 3][2 * lrow] = make_float2(avn.w, avn.w);
            Bs[nb][lcol + 0][lrow] = bvn.x; Bs[nb][lcol + 1][lrow] = bvn.y;
            Bs[nb][lcol + 2][lrow] = bvn.z; Bs[nb][lcol + 3][lrow] = bvn.w;
        }
        __syncthreads();
        buf ^= 1;
    }

    const int col0 = blockIdx.y * 128 + tx * 8;
    const int row0 = blockIdx.x * 128 + ty * 8;
    float badd[8];
#pragma unroll
    for (int j = 0; j < 8; j++) badd[j] = bias ? bias[col0 + j] : 0.f;
#pragma unroll
    for (int i = 0; i < 8; i++) {
        float o[8];
#pragma unroll
        for (int j = 0; j < 4; j++) {
            PackF2 p; p.u = acc[i][j];
            o[2 * j]     = p.f.x + badd[2 * j];
            o[2 * j + 1] = p.f.y + badd[2 * j + 1];
        }
        *(float4*)(C + (size_t)(row0 + i) * Ncols + col0)     = make_float4(o[0], o[1], o[2], o[3]);
        *(float4*)(C + (size_t)(row0 + i) * Ncols + col0 + 4) = make_float4(o[4], o[5], o[6], o[7]);
    }
}

// ---------------- conv1d as packed implicit-im2col GEMM ----------------
template<int KW>
__global__ __launch_bounds__(256) void conv_gemm(
    const float* __restrict__ W, const float* __restrict__ X,
    const float* __restrict__ bias, float* __restrict__ C,
    int Kp, int Ncols, int Lin, int Lout, int GLin)
{
    __shared__ float AsD[2][8][256];
    __shared__ float Bs [2][8][128];
    const int tid  = threadIdx.x;
    const int lrow = tid >> 1;
    const int lcol = (tid & 1) << 2;
    const int tx   = tid & 15;
    const int ty   = tid >> 4;

    const float* Ab = W + (size_t)blockIdx.y * 128 * Kp + (size_t)lrow * Kp + lcol;

    const int bn_l  = tid & 127;
    const int kb    = (tid >> 7) << 2;
    const int nglob = blockIdx.x * 128 + bn_l;
    const int g     = nglob / Lout;
    const int l     = nglob - g * Lout;
    const float* Xb = X + (size_t)g * Lin + l;

    unsigned long long acc[8][4];
#pragma unroll
    for (int i = 0; i < 8; i++)
#pragma unroll
        for (int j = 0; j < 4; j++) acc[i][j] = 0ull;

    {
        float4 av = *(const float4*)Ab;
        *(float2*)&AsD[0][lcol + 0][2 * lrow] = make_float2(av.x, av.x);
        *(float2*)&AsD[0][lcol + 1][2 * lrow] = make_float2(av.y, av.y);
        *(float2*)&AsD[0][lcol + 2][2 * lrow] = make_float2(av.z, av.z);
        *(float2*)&AsD[0][lcol + 3][2 * lrow] = make_float2(av.w, av.w);
#pragma unroll
        for (int i = 0; i < 4; i++) {
            const int kp = kb + i;
            const int ci = kp / KW;
            const int t  = kp - ci * KW;
            Bs[0][kb + i][bn_l] = Xb[(size_t)ci * GLin + t];
        }
    }
    __syncthreads();

    const int nk = Kp >> 3;
    int buf = 0;
    for (int kt = 0; kt < nk; kt++) {
        float4 avn;
        float  bvn[4];
        const bool has = (kt + 1) < nk;
        if (has) {
            avn = *(const float4*)(Ab + (kt + 1) * 8);
            const int k0 = (kt + 1) * 8;
#pragma unroll
            for (int i = 0; i < 4; i++) {
                const int kp = k0 + kb + i;
                const int ci = kp / KW;
                const int t  = kp - ci * KW;
                bvn[i] = Xb[(size_t)ci * GLin + t];
            }
        }
#pragma unroll
        for (int kk = 0; kk < 8; kk++) {
            const ulonglong2* ap = (const ulonglong2*)&AsD[buf][kk][ty * 16];
            const ulonglong2* bp = (const ulonglong2*)&Bs[buf][kk][tx * 8];
            ulonglong2 a01 = ap[0], a23 = ap[1], a45 = ap[2], a67 = ap[3];
            ulonglong2 b01 = bp[0], b23 = bp[1];
            unsigned long long a[8] = {a01.x, a01.y, a23.x, a23.y, a45.x, a45.y, a67.x, a67.y};
            unsigned long long bb[4] = {b01.x, b01.y, b23.x, b23.y};
#pragma unroll
            for (int i = 0; i < 8; i++)
#pragma unroll
                for (int j = 0; j < 4; j++) FMA2(acc[i][j], a[i], bb[j]);
        }
        if (has) {
            const int nb = buf ^ 1;
            *(float2*)&AsD[nb][lcol + 0][2 * lrow] = make_float2(avn.x, avn.x);
            *(float2*)&AsD[nb][lcol + 1][2 * lrow] = make_float2(avn.y, avn.y);
            *(float2*)&AsD[nb][lcol + 2][2 * lrow] = make_float2(avn.z, avn.z);
            *(float2*)&AsD[nb][lcol + 3][2 * lrow] = make_float2(avn.w, avn.w);
#pragma unroll
            for (int i = 0; i < 4; i++) Bs[nb][kb + i][bn_l] = bvn[i];
        }
        __syncthreads();
        buf ^= 1;
    }

    const int row0 = blockIdx.y * 128 + ty * 8;
    const int col0 = blockIdx.x * 128 + tx * 8;
#pragma unroll
    for (int i = 0; i < 8; i++) {
        const float bo = bias[row0 + i];
        float o[8];
#pragma unroll
        for (int j = 0; j < 4; j++) {
            PackF2 p; p.u = acc[i][j];
            o[2 * j]     = p.f.x + bo;
            o[2 * j + 1] = p.f.y + bo;
        }
        *(float4*)(C + (size_t)(row0 + i) * Ncols + col0)     = make_float4(o[0], o[1], o[2], o[3]);
        *(float4*)(C + (size_t)(row0 + i) * Ncols + col0 + 4) = make_float4(o[4], o[5], o[6], o[7]);
    }
}

// ---------------- edge scatter: agg[dst] += ew * m[src]  (vector RED, no return) ----------------
__global__ void scatter_kernel(const float* __restrict__ Msg, const int* __restrict__ ei,
                               const float* __restrict__ ew, float* __restrict__ AGG)
{
    const int t = blockIdx.x * blockDim.x + threadIdx.x;
    const int e = t >> 5;
    const int j = (t & 31) << 2;
    const int s = ei[e];
    const int d = ei[NE + e];
    const float w = ew[e];
    const float4 v = *(const float4*)(Msg + (size_t)s * DIM + j);
    float* b = AGG + (size_t)d * DIM + j;
    asm volatile("red.global.add.v4.f32 [%0], {%1, %2, %3, %4};"
                 :: "l"(b), "f"(v.x * w), "f"(v.y * w), "f"(v.z * w), "f"(v.w * w)
                 : "memory");
}

__device__ __forceinline__ float fast_sigmoid(float v)
{
    v = fminf(fmaxf(v, -30.f), 30.f);
    return 1.f / (1.f + __expf(-v));
}
__device__ __forceinline__ float fast_tanh(float v)
{
    v = fminf(fmaxf(v, -15.f), 15.f);
    const float e = __expf(-2.f * v);
    return (1.f - e) / (1.f + e);
}

// ---------------- GRU elementwise update (in-place on H), 4 channels/thread ----------------
__global__ void gru_kernel(const float* __restrict__ GX, const float* __restrict__ GH,
                           float* __restrict__ H)
{
    const int t = blockIdx.x * blockDim.x + threadIdx.x;   // N*32 threads
    const int i = t >> 5;
    const int j = (t & 31) << 2;
    const float* px = GX + (size_t)i * 384 + j;
    const float* ph = GH + (size_t)i * 384 + j;
    const float4 xr = *(const float4*)(px);
    const float4 xz = *(const float4*)(px + 128);
    const float4 xn = *(const float4*)(px + 256);
    const float4 hr = *(const float4*)(ph);
    const float4 hz = *(const float4*)(ph + 128);
    const float4 hn = *(const float4*)(ph + 256);
    float4* hp = (float4*)(H + (size_t)i * 128 + j);
    float4 h = *hp;
    float4 o;
    {
        const float r = fast_sigmoid(xr.x + hr.x);
        const float z = fast_sigmoid(xz.x + hz.x);
        const float n = fast_tanh(xn.x + r * hn.x);
        o.x = (1.f - z) * n + z * h.x;
    }
    {
        const float r = fast_sigmoid(xr.y + hr.y);
        const float z = fast_sigmoid(xz.y + hz.y);
        const float n = fast_tanh(xn.y + r * hn.y);
        o.y = (1.f - z) * n + z * h.y;
    }
    {
        const float r = fast_sigmoid(xr.z + hr.z);
        const float z = fast_sigmoid(xz.z + hz.z);
        const float n = fast_tanh(xn.z + r * hn.z);
        o.z = (1.f - z) * n + z * h.z;
    }
    {
        const float r = fast_sigmoid(xr.w + hr.w);
        const float z = fast_sigmoid(xz.w + hz.w);
        const float n = fast_tanh(xn.w + r * hn.w);
        o.w = (1.f - z) * n + z * h.w;
    }
    *hp = o;
}

// ---------------- [N,128] -> [128,N] transpose into CAT ----------------
__global__ void transpose_nd(const float* __restrict__ src, float* __restrict__ dst)
{
    __shared__ float tile[32][33];
    const int nb = blockIdx.x << 5;
    const int cb = blockIdx.y << 5;
    const int tx = threadIdx.x, ty = threadIdx.y;
#pragma unroll
    for (int i = 0; i < 32; i += 8)
        tile[ty + i][tx] = src[(size_t)(nb + ty + i) * DIM + cb + tx];
    __syncthreads();
#pragma unroll
    for (int i = 0; i < 32; i += 8)
        dst[(size_t)(cb + ty + i) * N_NODES + nb + tx] = tile[tx][ty + i];
}

// ---------------- transpose the 6 ggnn weight matrices ----------------
__global__ void transpose_w_kernel(const float* __restrict__ w, float* __restrict__ wT)
{
    const int t = blockIdx.x * 256 + threadIdx.x;
    const int s = t >> 14;
    const int j = (t >> 7) & 127;
    const int k = t & 127;
    wT[t] = w[(s << 14) + (k << 7) + j];
}

// ---------------- per-channel mean / rstd over [G*Lout] ----------------
__global__ void bnstats_kernel(const float* __restrict__ T, int len,
                               float* __restrict__ mean, float* __restrict__ rstd)
{
    __shared__ double sh[256], sh2[256];
    const int c = blockIdx.x;
    const float* p = T + (size_t)c * len;
    double s = 0.0, s2 = 0.0;
    for (int i = threadIdx.x; i < len; i += 256) {
        const double v = (double)p[i];
        s += v; s2 += v * v;
    }
    sh[threadIdx.x] = s; sh2[threadIdx.x] = s2;
    __syncthreads();
    for (int st = 128; st > 0; st >>= 1) {
        if (threadIdx.x < st) {
            sh[threadIdx.x]  += sh[threadIdx.x + st];
            sh2[threadIdx.x] += sh2[threadIdx.x + st];
        }
        __syncthreads();
    }
    if (threadIdx.x == 0) {
        const double m   = sh[0] / len;
        const double var = sh2[0] / len - m * m;
        mean[c] = (float)m;
        rstd[c] = (float)(1.0 / sqrt(var + 1e-5));
    }
}

// ---------------- fused BN(affine) + ReLU + MaxPool ----------------
template<int PK, int PS>
__global__ void bn_relu_pool(const float* __restrict__ T, const float* __restrict__ mean,
                             const float* __restrict__ rstd, const float* __restrict__ gamma,
                             const float* __restrict__ beta, float* __restrict__ O,
                             int Lin, int Lpool, int total)
{
    const int idx = blockIdx.x * 256 + threadIdx.x;
    if (idx >= total) return;
    const int lp   = idx % Lpool;
    const int rest = idx / Lpool;
    const int g    = rest & 127;
    const int c    = rest >> 7;
    const float* p = T + ((size_t)c * GR + g) * Lin + lp * PS;
    const float a = rstd[c] * gamma[c];
    const float b = beta[c] - mean[c] * a;
    float mx = 0.f;
#pragma unroll
    for (int t = 0; t < PK; t++) mx = fmaxf(mx, fmaf(p[t], a, b));
    O[idx] = mx;
}

// ---------------- readout ----------------
__global__ void final_kernel(const float* __restrict__ P2, const float* __restrict__ Q2,
                             const float* __restrict__ wy, const float* __restrict__ by,
                             const float* __restrict__ wz, const float* __restrict__ bz,
                             float* __restrict__ out)
{
    const int g = blockIdx.x;
    __shared__ float s0[128], s1[128];
    const int l = threadIdx.x;
    float a0 = 0.f, a1 = 0.f;
    if (l < 127) {
        float y0 = by[0], y1 = by[1];
#pragma unroll 4
        for (int d = 0; d < 128; d++) {
            const float v = P2[((size_t)d * GR + g) * 127 + l];
            y0 = fmaf(v, wy[d],        y0);
            y1 = fmaf(v, wy[128 + d],  y1);
        }
        float z0 = bz[0], z1 = bz[1];
#pragma unroll 4
        for (int cc = 0; cc < 256; cc++) {
            const float v = Q2[((size_t)cc * GR + g) * 127 + l];
            z0 = fmaf(v, wz[cc],       z0);
            z1 = fmaf(v, wz[256 + cc], z1);
        }
        a0 = y0 * z0; a1 = y1 * z1;
    }
    s0[l] = a0; s1[l] = a1;
    __syncthreads();
    for (int st = 64; st > 0; st >>= 1) {
        if (l < st) { s0[l] += s0[l + st]; s1[l] += s1[l + st]; }
        __syncthreads();
    }
    if (l == 0) {
        out[g * 2 + 0] = s0[0] / 127.f;
        out[g * 2 + 1] = s1[0] / 127.f;
    }
}

// ---------------- host orchestration ----------------
extern "C" void kernel_launch(void* const* d_in, const int* in_sizes, int n_in,
                              void* d_out, int out_size)
{
    const float* x    = (const float*)d_in[0];
    const int*   ei   = (const int*)  d_in[1];
    const float* ew   = (const float*)d_in[2];
    const float* ggw  = (const float*)d_in[4];
    const float* wih  = (const float*)d_in[5];
    const float* whh  = (const float*)d_in[6];
    const float* bih  = (const float*)d_in[7];
    const float* bhh  = (const float*)d_in[8];
    const float* c1w  = (const float*)d_in[9];
    const float* c1b  = (const float*)d_in[10];
    const float* c2w  = (const float*)d_in[11];
    const float* c2b  = (const float*)d_in[12];
    const float* cc1w = (const float*)d_in[13];
    const float* cc1b = (const float*)d_in[14];
    const float* cc2w = (const float*)d_in[15];
    const float* cc2b = (const float*)d_in[16];
    const float* bn1g = (const float*)d_in[17];
    const float* bn1b = (const float*)d_in[18];
    const float* bn2g = (const float*)d_in[19];
    const float* bn2b = (const float*)d_in[20];
    const float* myw  = (const float*)d_in[21];
    const float* myb  = (const float*)d_in[22];
    const float* mzw  = (const float*)d_in[23];
    const float* mzb  = (const float*)d_in[24];
    float* out = (float*)d_out;

    float *H, *Msg, *AGG, *GX, *GH, *WT, *CAT, *T1, *P1, *T2, *P2, *U1, *Q1, *U2, *Q2, *MEAN, *RSTD;
    cudaGetSymbolAddress((void**)&H,   g_H);
    cudaGetSymbolAddress((void**)&Msg, g_M);
    cudaGetSymbolAddress((void**)&AGG, g_AGG);
    cudaGetSymbolAddress((void**)&GX,  g_GX);
    cudaGetSymbolAddress((void**)&GH,  g_GH);
    cudaGetSymbolAddress((void**)&WT,  g_WT);
    cudaGetSymbolAddress((void**)&CAT, g_CAT);
    cudaGetSymbolAddress((void**)&T1,  g_T1);
    cudaGetSymbolAddress((void**)&P1,  g_P1);
    cudaGetSymbolAddress((void**)&T2,  g_T2);
    cudaGetSymbolAddress((void**)&P2,  g_P2);
    cudaGetSymbolAddress((void**)&U1,  g_U1);
    cudaGetSymbolAddress((void**)&Q1,  g_Q1);
    cudaGetSymbolAddress((void**)&U2,  g_U2);
    cudaGetSymbolAddress((void**)&Q2,  g_Q2);
    cudaGetSymbolAddress((void**)&MEAN, g_MEAN);
    cudaGetSymbolAddress((void**)&RSTD, g_RSTD);

    const size_t ndbytes = (size_t)N_NODES * DIM * sizeof(float);

    cudaMemcpyAsync(H, x, ndbytes, cudaMemcpyDeviceToDevice);
    transpose_w_kernel<<<(GSTEPS * DIM * DIM) / 256, 256>>>(ggw, WT);

    for (int s = 0; s < GSTEPS; s++) {
        gemm_nt<<<dim3(512, 1), 256>>>(H, WT + s * DIM * DIM, nullptr, Msg, 128, 128);
        cudaMemsetAsync(AGG, 0, ndbytes);
        scatter_kernel<<<(NE * 32) / 256, 256>>>(Msg, ei, ew, AGG);
        gemm_nt<<<dim3(512, 3), 256>>>(AGG, wih, bih, GX, 384, 128);
        gemm_nt<<<dim3(512, 3), 256>>>(H,   whh, bhh, GH, 384, 128);
        gru_kernel<<<(N_NODES * 32) / 256, 256>>>(GX, GH, H);
    }

    transpose_nd<<<dim3(N_NODES / 32, 4), dim3(32, 8)>>>(H, CAT);
    transpose_nd<<<dim3(N_NODES / 32, 4), dim3(32, 8)>>>(x, CAT + (size_t)128 * N_NODES);

    // ---- branch Y (h only, 128 ch) ----
    conv_gemm<3><<<dim3(510, 1), 256>>>(c1w, CAT, c1b, T1, 384, 65280, 512, 510, 65536);
    bnstats_kernel<<<128, 256>>>(T1, 65280, MEAN, RSTD);
    bn_relu_pool<3, 2><<<(128 * GR * 254) / 256, 256>>>(T1, MEAN, RSTD, bn1g, bn1b, P1, 510, 254, 128 * GR * 254);
    conv_gemm<1><<<dim3(254, 1), 256>>>(c2w, P1, c2b, T2, 128, 32512, 254, 254, 32512);
    bnstats_kernel<<<128, 256>>>(T2, 32512, MEAN, RSTD);
    bn_relu_pool<2, 2><<<(128 * GR * 127) / 256, 256>>>(T2, MEAN, RSTD, bn1g, bn1b, P2, 254, 127, 128 * GR * 127);

    // ---- branch Z (concat [h;x], 256 ch) ----
    conv_gemm<3><<<dim3(510, 2), 256>>>(cc1w, CAT, cc1b, U1, 768, 65280, 512, 510, 65536);
    bnstats_kernel<<<256, 256>>>(U1, 65280, MEAN, RSTD);
    bn_relu_pool<3, 2><<<(256 * GR * 254) / 256, 256>>>(U1, MEAN, RSTD, bn2g, bn2b, Q1, 510, 254, 256 * GR * 254);
    conv_gemm<1><<<dim3(254, 2), 256>>>(cc2w, Q1, cc2b, U2, 256, 32512, 254, 254, 32512);
    bnstats_kernel<<<256, 256>>>(U2, 32512, MEAN, RSTD);
    bn_relu_pool<2, 2><<<(256 * GR * 127) / 256, 256>>>(U2, MEAN, RSTD, bn2g, bn2b, Q2, 254, 127, 256 * GR * 127);

    final_kernel<<<GR, 128>>>(P2, Q2, myw, myb, mzw, mzb, out);
}

// round 9
// speedup vs baseline: 2.2051x; 2.2051x over previous
#include <cuda_runtime.h>
#include <cuda_bf16.h>
#include <math.h>
#include <stdint.h>

#define N_NODES 65536
#define DIM     128
#define GR      128
#define NE      262144
#define GSTEPS  6

// ---------------- scratch (static device allocations; no cudaMalloc) ----------------
__device__ float g_H  [N_NODES * DIM];
__device__ float g_M  [N_NODES * DIM];
__device__ float g_AGG[N_NODES * DIM];
__device__ float g_GX [N_NODES * 384];
__device__ float g_GH [N_NODES * 384];
__device__ float g_WT [GSTEPS * DIM * DIM];
__device__ float g_CAT[256 * N_NODES];
__device__ float g_T1 [128 * GR * 510];
__device__ float g_P1 [128 * GR * 254];
__device__ float g_T2 [128 * GR * 254];
__device__ float g_P2 [128 * GR * 127];
__device__ float g_U1 [256 * GR * 510];
__device__ float g_Q1 [256 * GR * 254];
__device__ float g_U2 [256 * GR * 254];
__device__ float g_Q2 [256 * GR * 127];
__device__ float g_MEAN[256];
__device__ float g_RSTD[256];
// bf16 split operands
__device__ __nv_bfloat16 g_Hhi [N_NODES * DIM];
__device__ __nv_bfloat16 g_Hlo [N_NODES * DIM];
__device__ __nv_bfloat16 g_Ahi [N_NODES * DIM];
__device__ __nv_bfloat16 g_Alo [N_NODES * DIM];
__device__ __nv_bfloat16 g_WThi[GSTEPS * DIM * DIM];
__device__ __nv_bfloat16 g_WTlo[GSTEPS * DIM * DIM];
__device__ __nv_bfloat16 g_IHhi[384 * DIM];
__device__ __nv_bfloat16 g_IHlo[384 * DIM];
__device__ __nv_bfloat16 g_HHhi[384 * DIM];
__device__ __nv_bfloat16 g_HHlo[384 * DIM];

__device__ __forceinline__ uint32_t smem_u32(const void* p) {
    uint32_t a;
    asm("{ .reg .u64 t; cvta.to.shared.u64 t, %1; cvt.u32.u64 %0, t; }" : "=r"(a) : "l"(p));
    return a;
}

// ================= warp-level mma.sync split-bf16 GEMM =================
// C[M,N] = A[M,128] * B[N,128]^T (+bias per col)
// via Ahi*Bhi + Ahi*Blo + Alo*Bhi, fp32 accumulate.
// 128x128 CTA tile, 8 warps (2x4), whole K=128 staged in smem once.
#define ROWB 272                      // padded row: 136 bf16 = 272 B (conflict-free ldmatrix)
#define TILEB (128 * ROWB)            // 34816 B per tile
#define OFF_AHI 0
#define OFF_ALO TILEB
#define OFF_BHI (2 * TILEB)
#define OFF_BLO (3 * TILEB)
#define MMA_SMEM (4 * TILEB)          // 139264 B

__global__ __launch_bounds__(256) void gemm_mma(
    const __nv_bfloat16* __restrict__ Ahi, const __nv_bfloat16* __restrict__ Alo,
    const __nv_bfloat16* __restrict__ Bhi, const __nv_bfloat16* __restrict__ Blo,
    const float* __restrict__ bias, float* __restrict__ C, int Ncols)
{
    extern __shared__ char sm[];
    const uint32_t sb = smem_u32(sm);
    const int tid  = threadIdx.x;
    const int wid  = tid >> 5;
    const int lane = tid & 31;

    // ---- cooperative load of 4 tiles (row-major, padded) ----
    {
        const int r    = tid & 127;
        const int kc   = (tid >> 7) << 6;           // 0 or 64
        const size_t ar = ((size_t)blockIdx.x * 128 + r) * 128 + kc;
        const size_t br = ((size_t)blockIdx.y * 128 + r) * 128 + kc;
        char* dst = sm + r * ROWB + kc * 2;
#pragma unroll
        for (int kk = 0; kk < 64; kk += 8) {
            *(uint4*)(dst + OFF_AHI + kk * 2) = *(const uint4*)(Ahi + ar + kk);
            *(uint4*)(dst + OFF_ALO + kk * 2) = *(const uint4*)(Alo + ar + kk);
            *(uint4*)(dst + OFF_BHI + kk * 2) = *(const uint4*)(Bhi + br + kk);
            *(uint4*)(dst + OFF_BLO + kk * 2) = *(const uint4*)(Blo + br + kk);
        }
    }
    __syncthreads();

    const int warpM = (wid >> 2) * 64;   // 0 or 64
    const int warpN = (wid & 3) * 32;    // 0,32,64,96

    float acc[4][4][4];
#pragma unroll
    for (int i = 0; i < 4; i++)
#pragma unroll
        for (int j = 0; j < 4; j++)
#pragma unroll
            for (int k = 0; k < 4; k++) acc[i][j][k] = 0.f;

    const uint32_t aoff[3] = {OFF_AHI, OFF_AHI, OFF_ALO};
    const uint32_t boff[3] = {OFF_BHI, OFF_BLO, OFF_BHI};

    const uint32_t a_r = warpM + (lane & 15);       // A ldmatrix row
    const uint32_t a_k = (lane >> 4) * 8;           // A ldmatrix k sub-offset
    const uint32_t b_r = warpN + (lane & 7);        // B ldmatrix row
    const uint32_t b_k = ((lane >> 3) & 1) * 8;

#pragma unroll
    for (int s = 0; s < 3; s++) {
        const uint32_t ab = sb + aoff[s];
        const uint32_t bb = sb + boff[s];
#pragma unroll
        for (int ks = 0; ks < 8; ks++) {
            uint32_t a[4][4], b[4][2];
#pragma unroll
            for (int mi = 0; mi < 4; mi++) {
                const uint32_t addr = ab + (a_r + mi * 16) * ROWB + (ks * 16 + a_k) * 2;
                asm volatile("ldmatrix.sync.aligned.m8n8.x4.shared.b16 {%0,%1,%2,%3}, [%4];"
                             : "=r"(a[mi][0]), "=r"(a[mi][1]), "=r"(a[mi][2]), "=r"(a[mi][3])
                             : "r"(addr));
            }
#pragma unroll
            for (int ni = 0; ni < 4; ni++) {
                const uint32_t addr = bb + (b_r + ni * 8) * ROWB + (ks * 16 + b_k) * 2;
                asm volatile("ldmatrix.sync.aligned.m8n8.x2.shared.b16 {%0,%1}, [%2];"
                             : "=r"(b[ni][0]), "=r"(b[ni][1]) : "r"(addr));
            }
#pragma unroll
            for (int mi = 0; mi < 4; mi++)
#pragma unroll
                for (int ni = 0; ni < 4; ni++) {
                    asm volatile(
                        "mma.sync.aligned.m16n8k16.row.col.f32.bf16.bf16.f32 "
                        "{%0,%1,%2,%3}, {%4,%5,%6,%7}, {%8,%9}, {%0,%1,%2,%3};"
                        : "+f"(acc[mi][ni][0]), "+f"(acc[mi][ni][1]),
                          "+f"(acc[mi][ni][2]), "+f"(acc[mi][ni][3])
                        : "r"(a[mi][0]), "r"(a[mi][1]), "r"(a[mi][2]), "r"(a[mi][3]),
                          "r"(b[ni][0]), "r"(b[ni][1]));
                }
        }
    }

    // ---- epilogue: fragment -> C (+bias) ----
    const int rbase = blockIdx.x * 128 + warpM + (lane >> 2);
    const int cbase = blockIdx.y * 128 + warpN + 2 * (lane & 3);
#pragma unroll
    for (int mi = 0; mi < 4; mi++) {
#pragma unroll
        for (int ni = 0; ni < 4; ni++) {
            const int row = rbase + mi * 16;
            const int col = cbase + ni * 8;
            float b0 = 0.f, b1 = 0.f;
            if (bias) { b0 = bias[col]; b1 = bias[col + 1]; }
            *(float2*)(C + (size_t)row * Ncols + col) =
                make_float2(acc[mi][ni][0] + b0, acc[mi][ni][1] + b1);
            *(float2*)(C + (size_t)(row + 8) * Ncols + col) =
                make_float2(acc[mi][ni][2] + b0, acc[mi][ni][3] + b1);
        }
    }
}

// ---------------- fp32 -> (bf16 hi, bf16 lo) split ----------------
__global__ void split_kernel(const float* __restrict__ X, __nv_bfloat16* __restrict__ hi,
                             __nv_bfloat16* __restrict__ lo, int n4)
{
    const int i = blockIdx.x * 256 + threadIdx.x;
    if (i >= n4) return;
    const float4 v = ((const float4*)X)[i];
    float fs[4] = {v.x, v.y, v.z, v.w};
    __nv_bfloat16 hb[4], lb[4];
#pragma unroll
    for (int j = 0; j < 4; j++) {
        hb[j] = __float2bfloat16(fs[j]);
        lb[j] = __float2bfloat16(fs[j] - __bfloat162float(hb[j]));
    }
    ((uint2*)hi)[i] = *(uint2*)hb;
    ((uint2*)lo)[i] = *(uint2*)lb;
}

// ---------------- conv1d as implicit-im2col GEMM (fp32, proven R3 version) ----------------
template<int KW>
__global__ __launch_bounds__(256) void conv_gemm(
    const float* __restrict__ W, const float* __restrict__ X,
    const float* __restrict__ bias, float* __restrict__ C,
    int Kp, int Ncols, int Lin, int Lout, int GLin)
{
    __shared__ float As[2][8][128];
    __shared__ float Bs[2][8][128];
    const int tid  = threadIdx.x;
    const int lrow = tid >> 1;
    const int lcol = (tid & 1) << 2;
    const int tx   = tid & 15;
    const int ty   = tid >> 4;

    const float* Ab = W + (size_t)blockIdx.y * 128 * Kp + (size_t)lrow * Kp + lcol;

    const int bn_l  = tid & 127;
    const int kb    = (tid >> 7) << 2;
    const int nglob = blockIdx.x * 128 + bn_l;
    const int g     = nglob / Lout;
    const int l     = nglob - g * Lout;
    const float* Xb = X + (size_t)g * Lin + l;

    float acc[8][8];
#pragma unroll
    for (int i = 0; i < 8; i++)
#pragma unroll
        for (int j = 0; j < 8; j++) acc[i][j] = 0.f;

    {
        float4 av = *(const float4*)Ab;
        As[0][lcol + 0][lrow] = av.x; As[0][lcol + 1][lrow] = av.y;
        As[0][lcol + 2][lrow] = av.z; As[0][lcol + 3][lrow] = av.w;
#pragma unroll
        for (int i = 0; i < 4; i++) {
            const int kp = kb + i;
            const int ci = kp / KW;
            const int t  = kp - ci * KW;
            Bs[0][kb + i][bn_l] = Xb[(size_t)ci * GLin + t];
        }
    }
    __syncthreads();

    const int nk = Kp >> 3;
    int buf = 0;
    for (int kt = 0; kt < nk; kt++) {
        float4 avn;
        float  bvn[4];
        const bool has = (kt + 1) < nk;
        if (has) {
            avn = *(const float4*)(Ab + (kt + 1) * 8);
            const int k0 = (kt + 1) * 8;
#pragma unroll
            for (int i = 0; i < 4; i++) {
                const int kp = k0 + kb + i;
                const int ci = kp / KW;
                const int t  = kp - ci * KW;
                bvn[i] = Xb[(size_t)ci * GLin + t];
            }
        }
        const float (*Ap)[128] = As[buf];
        const float (*Bp)[128] = Bs[buf];
#pragma unroll
        for (int kk = 0; kk < 8; kk++) {
            float a[8], b[8];
#pragma unroll
            for (int i = 0; i < 8; i++) a[i] = Ap[kk][ty * 8 + i];
#pragma unroll
            for (int j = 0; j < 8; j++) b[j] = Bp[kk][tx * 8 + j];
#pragma unroll
            for (int i = 0; i < 8; i++)
#pragma unroll
                for (int j = 0; j < 8; j++) acc[i][j] = fmaf(a[i], b[j], acc[i][j]);
        }
        if (has) {
            const int nb = buf ^ 1;
            As[nb][lcol + 0][lrow] = avn.x; As[nb][lcol + 1][lrow] = avn.y;
            As[nb][lcol + 2][lrow] = avn.z; As[nb][lcol + 3][lrow] = avn.w;
#pragma unroll
            for (int i = 0; i < 4; i++) Bs[nb][kb + i][bn_l] = bvn[i];
        }
        __syncthreads();
        buf ^= 1;
    }

    const int row0 = blockIdx.y * 128 + ty * 8;
    const int col0 = blockIdx.x * 128 + tx * 8;
#pragma unroll
    for (int i = 0; i < 8; i++) {
        const float bo = bias[row0 + i];
        float4 v0 = make_float4(acc[i][0] + bo, acc[i][1] + bo, acc[i][2] + bo, acc[i][3] + bo);
        float4 v1 = make_float4(acc[i][4] + bo, acc[i][5] + bo, acc[i][6] + bo, acc[i][7] + bo);
        *(float4*)(C + (size_t)(row0 + i) * Ncols + col0)     = v0;
        *(float4*)(C + (size_t)(row0 + i) * Ncols + col0 + 4) = v1;
    }
}

// ---------------- edge scatter: agg[dst] += ew * m[src] (vector RED) ----------------
__global__ void scatter_kernel(const float* __restrict__ Msg, const int* __restrict__ ei,
                               const float* __restrict__ ew, float* __restrict__ AGG)
{
    const int t = blockIdx.x * blockDim.x + threadIdx.x;
    const int e = t >> 5;
    const int j = (t & 31) << 2;
    const int s = ei[e];
    const int d = ei[NE + e];
    const float w = ew[e];
    const float4 v = *(const float4*)(Msg + (size_t)s * DIM + j);
    float* b = AGG + (size_t)d * DIM + j;
    asm volatile("red.global.add.v4.f32 [%0], {%1, %2, %3, %4};"
                 :: "l"(b), "f"(v.x * w), "f"(v.y * w), "f"(v.z * w), "f"(v.w * w)
                 : "memory");
}

__device__ __forceinline__ float fast_sigmoid(float v)
{
    v = fminf(fmaxf(v, -30.f), 30.f);
    return 1.f / (1.f + __expf(-v));
}
__device__ __forceinline__ float fast_tanh(float v)
{
    v = fminf(fmaxf(v, -15.f), 15.f);
    const float e = __expf(-2.f * v);
    return (1.f - e) / (1.f + e);
}

// ---------------- GRU elementwise update (in-place on H), 4 channels/thread ----------------
__global__ void gru_kernel(const float* __restrict__ GX, const float* __restrict__ GH,
                           float* __restrict__ H)
{
    const int t = blockIdx.x * blockDim.x + threadIdx.x;
    const int i = t >> 5;
    const int j = (t & 31) << 2;
    const float* px = GX + (size_t)i * 384 + j;
    const float* ph = GH + (size_t)i * 384 + j;
    const float4 xr = *(const float4*)(px);
    const float4 xz = *(const float4*)(px + 128);
    const float4 xn = *(const float4*)(px + 256);
    const float4 hr = *(const float4*)(ph);
    const float4 hz = *(const float4*)(ph + 128);
    const float4 hn = *(const float4*)(ph + 256);
    float4* hp = (float4*)(H + (size_t)i * 128 + j);
    float4 h = *hp;
    float4 o;
    { const float r = fast_sigmoid(xr.x + hr.x), z = fast_sigmoid(xz.x + hz.x);
      const float n = fast_tanh(xn.x + r * hn.x); o.x = (1.f - z) * n + z * h.x; }
    { const float r = fast_sigmoid(xr.y + hr.y), z = fast_sigmoid(xz.y + hz.y);
      const float n = fast_tanh(xn.y + r * hn.y); o.y = (1.f - z) * n + z * h.y; }
    { const float r = fast_sigmoid(xr.z + hr.z), z = fast_sigmoid(xz.z + hz.z);
      const float n = fast_tanh(xn.z + r * hn.z); o.z = (1.f - z) * n + z * h.z; }
    { const float r = fast_sigmoid(xr.w + hr.w), z = fast_sigmoid(xz.w + hz.w);
      const float n = fast_tanh(xn.w + r * hn.w); o.w = (1.f - z) * n + z * h.w; }
    *hp = o;
}

// ---------------- [N,128] -> [128,N] transpose into CAT ----------------
__global__ void transpose_nd(const float* __restrict__ src, float* __restrict__ dst)
{
    __shared__ float tile[32][33];
    const int nb = blockIdx.x << 5;
    const int cb = blockIdx.y << 5;
    const int tx = threadIdx.x, ty = threadIdx.y;
#pragma unroll
    for (int i = 0; i < 32; i += 8)
        tile[ty + i][tx] = src[(size_t)(nb + ty + i) * DIM + cb + tx];
    __syncthreads();
#pragma unroll
    for (int i = 0; i < 32; i += 8)
        dst[(size_t)(cb + ty + i) * N_NODES + nb + tx] = tile[tx][ty + i];
}

// ---------------- transpose the 6 ggnn weight matrices ----------------
__global__ void transpose_w_kernel(const float* __restrict__ w, float* __restrict__ wT)
{
    const int t = blockIdx.x * 256 + threadIdx.x;
    const int s = t >> 14;
    const int j = (t >> 7) & 127;
    const int k = t & 127;
    wT[t] = w[(s << 14) + (k << 7) + j];
}

// ---------------- per-channel mean / rstd over [G*Lout] ----------------
__global__ void bnstats_kernel(const float* __restrict__ T, int len,
                               float* __restrict__ mean, float* __restrict__ rstd)
{
    __shared__ double sh[256], sh2[256];
    const int c = blockIdx.x;
    const float* p = T + (size_t)c * len;
    double s = 0.0, s2 = 0.0;
    for (int i = threadIdx.x; i < len; i += 256) {
        const double v = (double)p[i];
        s += v; s2 += v * v;
    }
    sh[threadIdx.x] = s; sh2[threadIdx.x] = s2;
    __syncthreads();
    for (int st = 128; st > 0; st >>= 1) {
        if (threadIdx.x < st) {
            sh[threadIdx.x]  += sh[threadIdx.x + st];
            sh2[threadIdx.x] += sh2[threadIdx.x + st];
        }
        __syncthreads();
    }
    if (threadIdx.x == 0) {
        const double m   = sh[0] / len;
        const double var = sh2[0] / len - m * m;
        mean[c] = (float)m;
        rstd[c] = (float)(1.0 / sqrt(var + 1e-5));
    }
}

// ---------------- fused BN(affine) + ReLU + MaxPool ----------------
template<int PK, int PS>
__global__ void bn_relu_pool(const float* __restrict__ T, const float* __restrict__ mean,
                             const float* __restrict__ rstd, const float* __restrict__ gamma,
                             const float* __restrict__ beta, float* __restrict__ O,
                             int Lin, int Lpool, int total)
{
    const int idx = blockIdx.x * 256 + threadIdx.x;
    if (idx >= total) return;
    const int lp   = idx % Lpool;
    const int rest = idx / Lpool;
    const int g    = rest & 127;
    const int c    = rest >> 7;
    const float* p = T + ((size_t)c * GR + g) * Lin + lp * PS;
    const float a = rstd[c] * gamma[c];
    const float b = beta[c] - mean[c] * a;
    float mx = 0.f;
#pragma unroll
    for (int t = 0; t < PK; t++) mx = fmaxf(mx, fmaf(p[t], a, b));
    O[idx] = mx;
}

// ---------------- readout ----------------
__global__ void final_kernel(const float* __restrict__ P2, const float* __restrict__ Q2,
                             const float* __restrict__ wy, const float* __restrict__ by,
                             const float* __restrict__ wz, const float* __restrict__ bz,
                             float* __restrict__ out)
{
    const int g = blockIdx.x;
    __shared__ float s0[128], s1[128];
    const int l = threadIdx.x;
    float a0 = 0.f, a1 = 0.f;
    if (l < 127) {
        float y0 = by[0], y1 = by[1];
#pragma unroll 4
        for (int d = 0; d < 128; d++) {
            const float v = P2[((size_t)d * GR + g) * 127 + l];
            y0 = fmaf(v, wy[d],        y0);
            y1 = fmaf(v, wy[128 + d],  y1);
        }
        float z0 = bz[0], z1 = bz[1];
#pragma unroll 4
        for (int cc = 0; cc < 256; cc++) {
            const float v = Q2[((size_t)cc * GR + g) * 127 + l];
            z0 = fmaf(v, wz[cc],       z0);
            z1 = fmaf(v, wz[256 + cc], z1);
        }
        a0 = y0 * z0; a1 = y1 * z1;
    }
    s0[l] = a0; s1[l] = a1;
    __syncthreads();
    for (int st = 64; st > 0; st >>= 1) {
        if (l < st) { s0[l] += s0[l + st]; s1[l] += s1[l + st]; }
        __syncthreads();
    }
    if (l == 0) {
        out[g * 2 + 0] = s0[0] / 127.f;
        out[g * 2 + 1] = s1[0] / 127.f;
    }
}

// ---------------- host orchestration ----------------
extern "C" void kernel_launch(void* const* d_in, const int* in_sizes, int n_in,
                              void* d_out, int out_size)
{
    const float* x    = (const float*)d_in[0];
    const int*   ei   = (const int*)  d_in[1];
    const float* ew   = (const float*)d_in[2];
    const float* ggw  = (const float*)d_in[4];
    const float* wih  = (const float*)d_in[5];
    const float* whh  = (const float*)d_in[6];
    const float* bih  = (const float*)d_in[7];
    const float* bhh  = (const float*)d_in[8];
    const float* c1w  = (const float*)d_in[9];
    const float* c1b  = (const float*)d_in[10];
    const float* c2w  = (const float*)d_in[11];
    const float* c2b  = (const float*)d_in[12];
    const float* cc1w = (const float*)d_in[13];
    const float* cc1b = (const float*)d_in[14];
    const float* cc2w = (const float*)d_in[15];
    const float* cc2b = (const float*)d_in[16];
    const float* bn1g = (const float*)d_in[17];
    const float* bn1b = (const float*)d_in[18];
    const float* bn2g = (const float*)d_in[19];
    const float* bn2b = (const float*)d_in[20];
    const float* myw  = (const float*)d_in[21];
    const float* myb  = (const float*)d_in[22];
    const float* mzw  = (const float*)d_in[23];
    const float* mzb  = (const float*)d_in[24];
    float* out = (float*)d_out;

    float *H, *Msg, *AGG, *GX, *GH, *WT, *CAT, *T1, *P1, *T2, *P2, *U1, *Q1, *U2, *Q2, *MEAN, *RSTD;
    __nv_bfloat16 *Hhi, *Hlo, *Ahi, *Alo, *WThi, *WTlo, *IHhi, *IHlo, *HHhi, *HHlo;
    cudaGetSymbolAddress((void**)&H,   g_H);
    cudaGetSymbolAddress((void**)&Msg, g_M);
    cudaGetSymbolAddress((void**)&AGG, g_AGG);
    cudaGetSymbolAddress((void**)&GX,  g_GX);
    cudaGetSymbolAddress((void**)&GH,  g_GH);
    cudaGetSymbolAddress((void**)&WT,  g_WT);
    cudaGetSymbolAddress((void**)&CAT, g_CAT);
    cudaGetSymbolAddress((void**)&T1,  g_T1);
    cudaGetSymbolAddress((void**)&P1,  g_P1);
    cudaGetSymbolAddress((void**)&T2,  g_T2);
    cudaGetSymbolAddress((void**)&P2,  g_P2);
    cudaGetSymbolAddress((void**)&U1,  g_U1);
    cudaGetSymbolAddress((void**)&Q1,  g_Q1);
    cudaGetSymbolAddress((void**)&U2,  g_U2);
    cudaGetSymbolAddress((void**)&Q2,  g_Q2);
    cudaGetSymbolAddress((void**)&MEAN, g_MEAN);
    cudaGetSymbolAddress((void**)&RSTD, g_RSTD);
    cudaGetSymbolAddress((void**)&Hhi, g_Hhi);
    cudaGetSymbolAddress((void**)&Hlo, g_Hlo);
    cudaGetSymbolAddress((void**)&Ahi, g_Ahi);
    cudaGetSymbolAddress((void**)&Alo, g_Alo);
    cudaGetSymbolAddress((void**)&WThi, g_WThi);
    cudaGetSymbolAddress((void**)&WTlo, g_WTlo);
    cudaGetSymbolAddress((void**)&IHhi, g_IHhi);
    cudaGetSymbolAddress((void**)&IHlo, g_IHlo);
    cudaGetSymbolAddress((void**)&HHhi, g_HHhi);
    cudaGetSymbolAddress((void**)&HHlo, g_HHlo);

    cudaFuncSetAttribute(gemm_mma, cudaFuncAttributeMaxDynamicSharedMemorySize, MMA_SMEM);

    const size_t ndbytes = (size_t)N_NODES * DIM * sizeof(float);

    // h0 = x; transpose + split weights
    cudaMemcpyAsync(H, x, ndbytes, cudaMemcpyDeviceToDevice);
    transpose_w_kernel<<<(GSTEPS * DIM * DIM) / 256, 256>>>(ggw, WT);
    split_kernel<<<(GSTEPS * DIM * DIM / 4 + 255) / 256, 256>>>(WT,  WThi, WTlo, GSTEPS * DIM * DIM / 4);
    split_kernel<<<(384 * DIM / 4 + 255) / 256, 256>>>(wih, IHhi, IHlo, 384 * DIM / 4);
    split_kernel<<<(384 * DIM / 4 + 255) / 256, 256>>>(whh, HHhi, HHlo, 384 * DIM / 4);

    for (int s = 0; s < GSTEPS; s++) {
        // split current h
        split_kernel<<<(N_NODES * DIM / 4) / 256, 256>>>(H, Hhi, Hlo, N_NODES * DIM / 4);
        // m = h @ w[s]   (tensor cores)
        gemm_mma<<<dim3(512, 1), 256, MMA_SMEM>>>(Hhi, Hlo, WThi + s * DIM * DIM, WTlo + s * DIM * DIM,
                                                  nullptr, Msg, 128);
        // agg = scatter_add(ew * m[src] -> dst)
        cudaMemsetAsync(AGG, 0, ndbytes);
        scatter_kernel<<<(NE * 32) / 256, 256>>>(Msg, ei, ew, AGG);
        split_kernel<<<(N_NODES * DIM / 4) / 256, 256>>>(AGG, Ahi, Alo, N_NODES * DIM / 4);
        // gh = h @ whh^T + bhh ; gx = agg @ wih^T + bih   (tensor cores)
        gemm_mma<<<dim3(512, 3), 256, MMA_SMEM>>>(Hhi, Hlo, HHhi, HHlo, bhh, GH, 384);
        gemm_mma<<<dim3(512, 3), 256, MMA_SMEM>>>(Ahi, Alo, IHhi, IHlo, bih, GX, 384);
        // h = GRU(agg, h)
        gru_kernel<<<(N_NODES * 32) / 256, 256>>>(GX, GH, H);
    }

    transpose_nd<<<dim3(N_NODES / 32, 4), dim3(32, 8)>>>(H, CAT);
    transpose_nd<<<dim3(N_NODES / 32, 4), dim3(32, 8)>>>(x, CAT + (size_t)128 * N_NODES);

    // ---- branch Y (h only, 128 ch) ----
    conv_gemm<3><<<dim3(510, 1), 256>>>(c1w, CAT, c1b, T1, 384, 65280, 512, 510, 65536);
    bnstats_kernel<<<128, 256>>>(T1, 65280, MEAN, RSTD);
    bn_relu_pool<3, 2><<<(128 * GR * 254) / 256, 256>>>(T1, MEAN, RSTD, bn1g, bn1b, P1, 510, 254, 128 * GR * 254);
    conv_gemm<1><<<dim3(254, 1), 256>>>(c2w, P1, c2b, T2, 128, 32512, 254, 254, 32512);
    bnstats_kernel<<<128, 256>>>(T2, 32512, MEAN, RSTD);
    bn_relu_pool<2, 2><<<(128 * GR * 127) / 256, 256>>>(T2, MEAN, RSTD, bn1g, bn1b, P2, 254, 127, 128 * GR * 127);

    // ---- branch Z (concat [h;x], 256 ch) ----
    conv_gemm<3><<<dim3(510, 2), 256>>>(cc1w, CAT, cc1b, U1, 768, 65280, 512, 510, 65536);
    bnstats_kernel<<<256, 256>>>(U1, 65280, MEAN, RSTD);
    bn_relu_pool<3, 2><<<(256 * GR * 254) / 256, 256>>>(U1, MEAN, RSTD, bn2g, bn2b, Q1, 510, 254, 256 * GR * 254);
    conv_gemm<1><<<dim3(254, 2), 256>>>(cc2w, Q1, cc2b, U2, 256, 32512, 254, 254, 32512);
    bnstats_kernel<<<256, 256>>>(U2, 32512, MEAN, RSTD);
    bn_relu_pool<2, 2><<<(256 * GR * 127) / 256, 256>>>(U2, MEAN, RSTD, bn2g, bn2b, Q2, 254, 127, 256 * GR * 127);

    final_kernel<<<GR, 128>>>(P2, Q2, myw, myb, mzw, mzb, out);
}

// round 10
// speedup vs baseline: 2.5260x; 1.1455x over previous
#include <cuda_runtime.h>
#include <cuda_bf16.h>
#include <math.h>
#include <stdint.h>

#define N_NODES 65536
#define DIM     128
#define GR      128
#define NE      262144
#define GSTEPS  6

// ---------------- scratch (static device allocations; no cudaMalloc) ----------------
__device__ float g_H  [N_NODES * DIM];
__device__ float g_M  [N_NODES * DIM];
__device__ float g_AGG[N_NODES * DIM];
__device__ float g_GX [N_NODES * 384];
__device__ float g_GH [N_NODES * 384];
__device__ float g_WT [GSTEPS * DIM * DIM];
__device__ float g_CAT[256 * N_NODES];
__device__ float g_T1 [128 * GR * 512];      // stride 512; l=510,511 garbage (masked)
__device__ float g_U1 [256 * GR * 512];
__device__ float g_T2 [128 * GR * 254];
__device__ float g_U2 [256 * GR * 254];
__device__ float g_P2 [128 * GR * 127];
__device__ float g_Q2 [256 * GR * 127];
__device__ float g_MEAN[256];
__device__ float g_RSTD[256];
// bf16 split operands
__device__ __nv_bfloat16 g_Hhi [N_NODES * DIM];
__device__ __nv_bfloat16 g_Hlo [N_NODES * DIM];
__device__ __nv_bfloat16 g_Ahi [N_NODES * DIM];
__device__ __nv_bfloat16 g_Alo [N_NODES * DIM];
__device__ __nv_bfloat16 g_WThi[GSTEPS * DIM * DIM];
__device__ __nv_bfloat16 g_WTlo[GSTEPS * DIM * DIM];
__device__ __nv_bfloat16 g_IHhi[384 * DIM];
__device__ __nv_bfloat16 g_IHlo[384 * DIM];
__device__ __nv_bfloat16 g_HHhi[384 * DIM];
__device__ __nv_bfloat16 g_HHlo[384 * DIM];
__device__ __nv_bfloat16 g_CAThi[256 * N_NODES + 256];
__device__ __nv_bfloat16 g_CATlo[256 * N_NODES + 256];
__device__ __nv_bfloat16 g_P1hi[128 * GR * 254 + 256];
__device__ __nv_bfloat16 g_P1lo[128 * GR * 254 + 256];
__device__ __nv_bfloat16 g_Q1hi[256 * GR * 254 + 256];
__device__ __nv_bfloat16 g_Q1lo[256 * GR * 254 + 256];
// conv weights reordered [t][co][ci], split
__device__ __nv_bfloat16 g_CW1hi[3 * 128 * 128], g_CW1lo[3 * 128 * 128];
__device__ __nv_bfloat16 g_CW2hi[128 * 128],     g_CW2lo[128 * 128];
__device__ __nv_bfloat16 g_CC1hi[3 * 256 * 256], g_CC1lo[3 * 256 * 256];
__device__ __nv_bfloat16 g_CC2hi[256 * 256],     g_CC2lo[256 * 256];

__device__ __forceinline__ uint32_t smem_u32(const void* p) {
    uint32_t a;
    asm("{ .reg .u64 t; cvta.to.shared.u64 t, %1; cvt.u32.u64 %0, t; }" : "=r"(a) : "l"(p));
    return a;
}

// ================= warp-level mma.sync split-bf16 GEMM (verified R7) =================
#define ROWB 272
#define TILEB (128 * ROWB)
#define OFF_AHI 0
#define OFF_ALO TILEB
#define OFF_BHI (2 * TILEB)
#define OFF_BLO (3 * TILEB)
#define MMA_SMEM (4 * TILEB)

__global__ __launch_bounds__(256) void gemm_mma(
    const __nv_bfloat16* __restrict__ Ahi, const __nv_bfloat16* __restrict__ Alo,
    const __nv_bfloat16* __restrict__ Bhi, const __nv_bfloat16* __restrict__ Blo,
    const float* __restrict__ bias, float* __restrict__ C, int Ncols)
{
    extern __shared__ char sm[];
    const uint32_t sb = smem_u32(sm);
    const int tid  = threadIdx.x;
    const int wid  = tid >> 5;
    const int lane = tid & 31;

    {
        const int r    = tid & 127;
        const int kc   = (tid >> 7) << 6;
        const size_t ar = ((size_t)blockIdx.x * 128 + r) * 128 + kc;
        const size_t br = ((size_t)blockIdx.y * 128 + r) * 128 + kc;
        char* dst = sm + r * ROWB + kc * 2;
#pragma unroll
        for (int kk = 0; kk < 64; kk += 8) {
            *(uint4*)(dst + OFF_AHI + kk * 2) = *(const uint4*)(Ahi + ar + kk);
            *(uint4*)(dst + OFF_ALO + kk * 2) = *(const uint4*)(Alo + ar + kk);
            *(uint4*)(dst + OFF_BHI + kk * 2) = *(const uint4*)(Bhi + br + kk);
            *(uint4*)(dst + OFF_BLO + kk * 2) = *(const uint4*)(Blo + br + kk);
        }
    }
    __syncthreads();

    const int warpM = (wid >> 2) * 64;
    const int warpN = (wid & 3) * 32;

    float acc[4][4][4];
#pragma unroll
    for (int i = 0; i < 4; i++)
#pragma unroll
        for (int j = 0; j < 4; j++)
#pragma unroll
            for (int k = 0; k < 4; k++) acc[i][j][k] = 0.f;

    const uint32_t aoff[3] = {OFF_AHI, OFF_AHI, OFF_ALO};
    const uint32_t boff[3] = {OFF_BHI, OFF_BLO, OFF_BHI};

    const uint32_t a_r = warpM + (lane & 15);
    const uint32_t a_k = (lane >> 4) * 8;
    const uint32_t b_r = warpN + (lane & 7);
    const uint32_t b_k = ((lane >> 3) & 1) * 8;

#pragma unroll
    for (int s = 0; s < 3; s++) {
        const uint32_t ab = sb + aoff[s];
        const uint32_t bb = sb + boff[s];
#pragma unroll
        for (int ks = 0; ks < 8; ks++) {
            uint32_t a[4][4], b[4][2];
#pragma unroll
            for (int mi = 0; mi < 4; mi++) {
                const uint32_t addr = ab + (a_r + mi * 16) * ROWB + (ks * 16 + a_k) * 2;
                asm volatile("ldmatrix.sync.aligned.m8n8.x4.shared.b16 {%0,%1,%2,%3}, [%4];"
                             : "=r"(a[mi][0]), "=r"(a[mi][1]), "=r"(a[mi][2]), "=r"(a[mi][3])
                             : "r"(addr));
            }
#pragma unroll
            for (int ni = 0; ni < 4; ni++) {
                const uint32_t addr = bb + (b_r + ni * 8) * ROWB + (ks * 16 + b_k) * 2;
                asm volatile("ldmatrix.sync.aligned.m8n8.x2.shared.b16 {%0,%1}, [%2];"
                             : "=r"(b[ni][0]), "=r"(b[ni][1]) : "r"(addr));
            }
#pragma unroll
            for (int mi = 0; mi < 4; mi++)
#pragma unroll
                for (int ni = 0; ni < 4; ni++) {
                    asm volatile(
                        "mma.sync.aligned.m16n8k16.row.col.f32.bf16.bf16.f32 "
                        "{%0,%1,%2,%3}, {%4,%5,%6,%7}, {%8,%9}, {%0,%1,%2,%3};"
                        : "+f"(acc[mi][ni][0]), "+f"(acc[mi][ni][1]),
                          "+f"(acc[mi][ni][2]), "+f"(acc[mi][ni][3])
                        : "r"(a[mi][0]), "r"(a[mi][1]), "r"(a[mi][2]), "r"(a[mi][3]),
                          "r"(b[ni][0]), "r"(b[ni][1]));
                }
        }
    }

    const int rbase = blockIdx.x * 128 + warpM + (lane >> 2);
    const int cbase = blockIdx.y * 128 + warpN + 2 * (lane & 3);
#pragma unroll
    for (int mi = 0; mi < 4; mi++) {
#pragma unroll
        for (int ni = 0; ni < 4; ni++) {
            const int row = rbase + mi * 16;
            const int col = cbase + ni * 8;
            float b0 = 0.f, b1 = 0.f;
            if (bias) { b0 = bias[col]; b1 = bias[col + 1]; }
            *(float2*)(C + (size_t)row * Ncols + col) =
                make_float2(acc[mi][ni][0] + b0, acc[mi][ni][1] + b1);
            *(float2*)(C + (size_t)(row + 8) * Ncols + col) =
                make_float2(acc[mi][ni][2] + b0, acc[mi][ni][3] + b1);
        }
    }
}

// ================= conv as split-bf16 mma GEMM =================
// C[co][n] = sum_{t,ci} W[t][co][ci] * X[ci][n + t]   (NS = row stride of X and C)
// B tile (X) staged once per ci-chunk with 130 rows; tap shift t = ldmatrix base + t*ROWB.
#define CB_ROWS 130
#define CBTILE (CB_ROWS * ROWB)
#define C_AHI 0
#define C_ALO TILEB
#define C_BHI (2 * TILEB)
#define C_BLO (2 * TILEB + CBTILE)
#define CONV_SMEM (2 * TILEB + 2 * CBTILE)

__global__ __launch_bounds__(256) void conv_mma(
    const __nv_bfloat16* __restrict__ Whi, const __nv_bfloat16* __restrict__ Wlo,
    const __nv_bfloat16* __restrict__ Xhi, const __nv_bfloat16* __restrict__ Xlo,
    const float* __restrict__ bias, float* __restrict__ C,
    int Cout, int Cin, int KW, int NS)
{
    extern __shared__ char sm[];
    const uint32_t sb = smem_u32(sm);
    const int tid  = threadIdx.x;
    const int wid  = tid >> 5;
    const int lane = tid & 31;
    const int n0   = blockIdx.x * 128;
    const int cob  = blockIdx.y * 128;

    const int warpM = (wid >> 2) * 64;
    const int warpN = (wid & 3) * 32;

    float acc[4][4][4];
#pragma unroll
    for (int i = 0; i < 4; i++)
#pragma unroll
        for (int j = 0; j < 4; j++)
#pragma unroll
            for (int k = 0; k < 4; k++) acc[i][j][k] = 0.f;

    const uint32_t a_r = warpM + (lane & 15);
    const uint32_t a_k = (lane >> 4) * 8;
    const uint32_t b_r = warpN + (lane & 7);
    const uint32_t b_k = ((lane >> 3) & 1) * 8;

    const int nkc = Cin >> 7;
    for (int kc = 0; kc < nkc; kc++) {
        const int ci0 = kc << 7;
        __syncthreads();
        // ---- stage B (X) rows 0..129, k = ci within chunk ----
        {
            const int nn = tid & 127;
            const int kst = tid >> 7;
            const __nv_bfloat16* ph = Xhi + (size_t)(ci0 + kst) * NS + n0 + nn;
            const __nv_bfloat16* pl = Xlo + (size_t)(ci0 + kst) * NS + n0 + nn;
            char* dh = sm + C_BHI + nn * ROWB + kst * 2;
            char* dl = sm + C_BLO + nn * ROWB + kst * 2;
#pragma unroll 8
            for (int j = 0; j < 64; j++) {
                *(__nv_bfloat16*)dh = *ph;
                *(__nv_bfloat16*)dl = *pl;
                ph += 2 * (size_t)NS; pl += 2 * (size_t)NS;
                dh += 4; dl += 4;
            }
            // extra rows 128,129 (tap shifts)
            const int k2 = tid & 127;
            const int re = 128 + (tid >> 7);
            *(__nv_bfloat16*)(sm + C_BHI + re * ROWB + k2 * 2) = Xhi[(size_t)(ci0 + k2) * NS + n0 + re];
            *(__nv_bfloat16*)(sm + C_BLO + re * ROWB + k2 * 2) = Xlo[(size_t)(ci0 + k2) * NS + n0 + re];
        }
        for (int t = 0; t < KW; t++) {
            __syncthreads();
            // ---- stage A (weights) for this tap ----
            {
                const int r  = tid & 127;
                const int kh = (tid >> 7) << 6;
                const size_t src = ((size_t)(t * Cout + cob + r)) * Cin + ci0 + kh;
                char* da = sm + C_AHI + r * ROWB + kh * 2;
                char* dl = sm + C_ALO + r * ROWB + kh * 2;
#pragma unroll
                for (int kk = 0; kk < 64; kk += 8) {
                    *(uint4*)(da + kk * 2) = *(const uint4*)(Whi + src + kk);
                    *(uint4*)(dl + kk * 2) = *(const uint4*)(Wlo + src + kk);
                }
            }
            __syncthreads();
            const uint32_t aoffs[3] = {C_AHI, C_AHI, C_ALO};
            const uint32_t boffs[3] = {C_BHI, C_BLO, C_BHI};
#pragma unroll
            for (int s = 0; s < 3; s++) {
                const uint32_t ab = sb + aoffs[s];
                const uint32_t bb = sb + boffs[s] + (uint32_t)t * ROWB;
#pragma unroll
                for (int ks = 0; ks < 8; ks++) {
                    uint32_t a[4][4], b[4][2];
#pragma unroll
                    for (int mi = 0; mi < 4; mi++) {
                        const uint32_t addr = ab + (a_r + mi * 16) * ROWB + (ks * 16 + a_k) * 2;
                        asm volatile("ldmatrix.sync.aligned.m8n8.x4.shared.b16 {%0,%1,%2,%3}, [%4];"
                                     : "=r"(a[mi][0]), "=r"(a[mi][1]), "=r"(a[mi][2]), "=r"(a[mi][3])
                                     : "r"(addr));
                    }
#pragma unroll
                    for (int ni = 0; ni < 4; ni++) {
                        const uint32_t addr = bb + (b_r + ni * 8) * ROWB + (ks * 16 + b_k) * 2;
                        asm volatile("ldmatrix.sync.aligned.m8n8.x2.shared.b16 {%0,%1}, [%2];"
                                     : "=r"(b[ni][0]), "=r"(b[ni][1]) : "r"(addr));
                    }
#pragma unroll
                    for (int mi = 0; mi < 4; mi++)
#pragma unroll
                        for (int ni = 0; ni < 4; ni++) {
                            asm volatile(
                                "mma.sync.aligned.m16n8k16.row.col.f32.bf16.bf16.f32 "
                                "{%0,%1,%2,%3}, {%4,%5,%6,%7}, {%8,%9}, {%0,%1,%2,%3};"
                                : "+f"(acc[mi][ni][0]), "+f"(acc[mi][ni][1]),
                                  "+f"(acc[mi][ni][2]), "+f"(acc[mi][ni][3])
                                : "r"(a[mi][0]), "r"(a[mi][1]), "r"(a[mi][2]), "r"(a[mi][3]),
                                  "r"(b[ni][0]), "r"(b[ni][1]));
                        }
                }
            }
        }
    }

    // ---- epilogue: bias per output row (channel) ----
    const int rb  = cob + warpM + (lane >> 2);
    const int cb2 = n0 + warpN + 2 * (lane & 3);
#pragma unroll
    for (int mi = 0; mi < 4; mi++) {
#pragma unroll
        for (int ni = 0; ni < 4; ni++) {
            const int row = rb + mi * 16;
            const int col = cb2 + ni * 8;
            const float b0 = bias[row];
            const float b1 = bias[row + 8];
            *(float2*)(C + (size_t)row * NS + col) =
                make_float2(acc[mi][ni][0] + b0, acc[mi][ni][1] + b0);
            *(float2*)(C + (size_t)(row + 8) * NS + col) =
                make_float2(acc[mi][ni][2] + b1, acc[mi][ni][3] + b1);
        }
    }
}

// ---------------- fp32 -> (bf16 hi, bf16 lo) split ----------------
__global__ void split_kernel(const float* __restrict__ X, __nv_bfloat16* __restrict__ hi,
                             __nv_bfloat16* __restrict__ lo, int n4)
{
    const int i = blockIdx.x * 256 + threadIdx.x;
    if (i >= n4) return;
    const float4 v = ((const float4*)X)[i];
    float fs[4] = {v.x, v.y, v.z, v.w};
    __nv_bfloat16 hb[4], lb[4];
#pragma unroll
    for (int j = 0; j < 4; j++) {
        hb[j] = __float2bfloat16(fs[j]);
        lb[j] = __float2bfloat16(fs[j] - __bfloat162float(hb[j]));
    }
    ((uint2*)hi)[i] = *(uint2*)hb;
    ((uint2*)lo)[i] = *(uint2*)lb;
}

// ---------------- conv weight reorder+split: w[co][ci][t] -> [t][co][ci] hi/lo ----------------
__global__ void convw_prep(const float* __restrict__ w, __nv_bfloat16* __restrict__ hi,
                           __nv_bfloat16* __restrict__ lo, int Cout, int Cin, int KW)
{
    const int idx = blockIdx.x * 256 + threadIdx.x;
    if (idx >= KW * Cout * Cin) return;
    const int ci = idx % Cin;
    const int co = (idx / Cin) % Cout;
    const int t  = idx / (Cin * Cout);
    const float v = w[((size_t)co * Cin + ci) * KW + t];
    const __nv_bfloat16 h = __float2bfloat16(v);
    hi[idx] = h;
    lo[idx] = __float2bfloat16(v - __bfloat162float(h));
}

// ---------------- edge scatter: agg[dst] += ew * m[src] (vector RED) ----------------
__global__ void scatter_kernel(const float* __restrict__ Msg, const int* __restrict__ ei,
                               const float* __restrict__ ew, float* __restrict__ AGG)
{
    const int t = blockIdx.x * blockDim.x + threadIdx.x;
    const int e = t >> 5;
    const int j = (t & 31) << 2;
    const int s = ei[e];
    const int d = ei[NE + e];
    const float w = ew[e];
    const float4 v = *(const float4*)(Msg + (size_t)s * DIM + j);
    float* b = AGG + (size_t)d * DIM + j;
    asm volatile("red.global.add.v4.f32 [%0], {%1, %2, %3, %4};"
                 :: "l"(b), "f"(v.x * w), "f"(v.y * w), "f"(v.z * w), "f"(v.w * w)
                 : "memory");
}

__device__ __forceinline__ float fast_sigmoid(float v)
{
    v = fminf(fmaxf(v, -30.f), 30.f);
    return 1.f / (1.f + __expf(-v));
}
__device__ __forceinline__ float fast_tanh(float v)
{
    v = fminf(fmaxf(v, -15.f), 15.f);
    const float e = __expf(-2.f * v);
    return (1.f - e) / (1.f + e);
}

// ---------------- GRU update, in-place on H, fused bf16 split output ----------------
__global__ void gru_kernel(const float* __restrict__ GX, const float* __restrict__ GH,
                           float* __restrict__ H, __nv_bfloat16* __restrict__ Hhi,
                           __nv_bfloat16* __restrict__ Hlo)
{
    const int t = blockIdx.x * blockDim.x + threadIdx.x;
    const int i = t >> 5;
    const int j = (t & 31) << 2;
    const float* px = GX + (size_t)i * 384 + j;
    const float* ph = GH + (size_t)i * 384 + j;
    const float4 xr = *(const float4*)(px);
    const float4 xz = *(const float4*)(px + 128);
    const float4 xn = *(const float4*)(px + 256);
    const float4 hr = *(const float4*)(ph);
    const float4 hz = *(const float4*)(ph + 128);
    const float4 hn = *(const float4*)(ph + 256);
    float4* hp = (float4*)(H + (size_t)i * 128 + j);
    float4 h = *hp;
    float4 o;
    { const float r = fast_sigmoid(xr.x + hr.x), z = fast_sigmoid(xz.x + hz.x);
      const float n = fast_tanh(xn.x + r * hn.x); o.x = (1.f - z) * n + z * h.x; }
    { const float r = fast_sigmoid(xr.y + hr.y), z = fast_sigmoid(xz.y + hz.y);
      const float n = fast_tanh(xn.y + r * hn.y); o.y = (1.f - z) * n + z * h.y; }
    { const float r = fast_sigmoid(xr.z + hr.z), z = fast_sigmoid(xz.z + hz.z);
      const float n = fast_tanh(xn.z + r * hn.z); o.z = (1.f - z) * n + z * h.z; }
    { const float r = fast_sigmoid(xr.w + hr.w), z = fast_sigmoid(xz.w + hz.w);
      const float n = fast_tanh(xn.w + r * hn.w); o.w = (1.f - z) * n + z * h.w; }
    *hp = o;
    float fs[4] = {o.x, o.y, o.z, o.w};
    __nv_bfloat16 hb[4], lb[4];
#pragma unroll
    for (int q = 0; q < 4; q++) {
        hb[q] = __float2bfloat16(fs[q]);
        lb[q] = __float2bfloat16(fs[q] - __bfloat162float(hb[q]));
    }
    const size_t e4 = ((size_t)i * 128 + j) >> 2;
    ((uint2*)Hhi)[e4] = *(uint2*)hb;
    ((uint2*)Hlo)[e4] = *(uint2*)lb;
}

// ---------------- [N,128] -> [128,N] transpose into CAT ----------------
__global__ void transpose_nd(const float* __restrict__ src, float* __restrict__ dst)
{
    __shared__ float tile[32][33];
    const int nb = blockIdx.x << 5;
    const int cb = blockIdx.y << 5;
    const int tx = threadIdx.x, ty = threadIdx.y;
#pragma unroll
    for (int i = 0; i < 32; i += 8)
        tile[ty + i][tx] = src[(size_t)(nb + ty + i) * DIM + cb + tx];
    __syncthreads();
#pragma unroll
    for (int i = 0; i < 32; i += 8)
        dst[(size_t)(cb + ty + i) * N_NODES + nb + tx] = tile[tx][ty + i];
}

// ---------------- transpose the 6 ggnn weight matrices ----------------
__global__ void transpose_w_kernel(const float* __restrict__ w, float* __restrict__ wT)
{
    const int t = blockIdx.x * 256 + threadIdx.x;
    const int s = t >> 14;
    const int j = (t >> 7) & 127;
    const int k = t & 127;
    wT[t] = w[(s << 14) + (k << 7) + j];
}

// ---------------- BN stats: plain (contiguous len) ----------------
__global__ void bnstats_kernel(const float* __restrict__ T, int len,
                               float* __restrict__ mean, float* __restrict__ rstd)
{
    __shared__ double sh[256], sh2[256];
    const int c = blockIdx.x;
    const float* p = T + (size_t)c * len;
    double s = 0.0, s2 = 0.0;
    for (int i = threadIdx.x; i < len; i += 256) {
        const double v = (double)p[i];
        s += v; s2 += v * v;
    }
    sh[threadIdx.x] = s; sh2[threadIdx.x] = s2;
    __syncthreads();
    for (int st = 128; st > 0; st >>= 1) {
        if (threadIdx.x < st) {
            sh[threadIdx.x]  += sh[threadIdx.x + st];
            sh2[threadIdx.x] += sh2[threadIdx.x + st];
        }
        __syncthreads();
    }
    if (threadIdx.x == 0) {
        const double m   = sh[0] / len;
        const double var = sh2[0] / len - m * m;
        mean[c] = (float)m;
        rstd[c] = (float)(1.0 / sqrt(var + 1e-5));
    }
}

// ---------------- BN stats over [GR][512] with l<510 valid ----------------
__global__ void bnstats_mask(const float* __restrict__ T,
                             float* __restrict__ mean, float* __restrict__ rstd)
{
    __shared__ double sh[256], sh2[256];
    const int c = blockIdx.x;
    const float* p = T + (size_t)c * GR * 512;
    double s = 0.0, s2 = 0.0;
    for (int i = threadIdx.x; i < GR * 512; i += 256) {
        if ((i & 511) < 510) {
            const double v = (double)p[i];
            s += v; s2 += v * v;
        }
    }
    sh[threadIdx.x] = s; sh2[threadIdx.x] = s2;
    __syncthreads();
    for (int st = 128; st > 0; st >>= 1) {
        if (threadIdx.x < st) {
            sh[threadIdx.x]  += sh[threadIdx.x + st];
            sh2[threadIdx.x] += sh2[threadIdx.x + st];
        }
        __syncthreads();
    }
    if (threadIdx.x == 0) {
        const double len = (double)(GR * 510);
        const double m   = sh[0] / len;
        const double var = sh2[0] / len - m * m;
        mean[c] = (float)m;
        rstd[c] = (float)(1.0 / sqrt(var + 1e-5));
    }
}

// ---------------- fused BN + ReLU + MaxPool, fp32 output ----------------
template<int PK, int PS>
__global__ void pool_f32(const float* __restrict__ T, const float* __restrict__ mean,
                         const float* __restrict__ rstd, const float* __restrict__ gamma,
                         const float* __restrict__ beta, float* __restrict__ O,
                         int LinStride, int Lpool, int total)
{
    const int idx = blockIdx.x * 256 + threadIdx.x;
    if (idx >= total) return;
    const int lp   = idx % Lpool;
    const int rest = idx / Lpool;
    const int g    = rest & 127;
    const int c    = rest >> 7;
    const float* p = T + ((size_t)c * GR + g) * LinStride + lp * PS;
    const float a = rstd[c] * gamma[c];
    const float b = beta[c] - mean[c] * a;
    float mx = 0.f;
#pragma unroll
    for (int t = 0; t < PK; t++) mx = fmaxf(mx, fmaf(p[t], a, b));
    O[idx] = mx;
}

// ---------------- fused BN + ReLU + MaxPool, bf16-split output ----------------
template<int PK, int PS>
__global__ void pool_bf16(const float* __restrict__ T, const float* __restrict__ mean,
                          const float* __restrict__ rstd, const float* __restrict__ gamma,
                          const float* __restrict__ beta,
                          __nv_bfloat16* __restrict__ Ohi, __nv_bfloat16* __restrict__ Olo,
                          int LinStride, int Lpool, int total)
{
    const int idx = blockIdx.x * 256 + threadIdx.x;
    if (idx >= total) return;
    const int lp   = idx % Lpool;
    const int rest = idx / Lpool;
    const int g    = rest & 127;
    const int c    = rest >> 7;
    const float* p = T + ((size_t)c * GR + g) * LinStride + lp * PS;
    const float a = rstd[c] * gamma[c];
    const float b = beta[c] - mean[c] * a;
    float mx = 0.f;
#pragma unroll
    for (int t = 0; t < PK; t++) mx = fmaxf(mx, fmaf(p[t], a, b));
    const __nv_bfloat16 h = __float2bfloat16(mx);
    Ohi[idx] = h;
    Olo[idx] = __float2bfloat16(mx - __bfloat162float(h));
}

// ---------------- readout ----------------
__global__ void final_kernel(const float* __restrict__ P2, const float* __restrict__ Q2,
                             const float* __restrict__ wy, const float* __restrict__ by,
                             const float* __restrict__ wz, const float* __restrict__ bz,
                             float* __restrict__ out)
{
    const int g = blockIdx.x;
    __shared__ float s0[128], s1[128];
    const int l = threadIdx.x;
    float a0 = 0.f, a1 = 0.f;
    if (l < 127) {
        float y0 = by[0], y1 = by[1];
#pragma unroll 4
        for (int d = 0; d < 128; d++) {
            const float v = P2[((size_t)d * GR + g) * 127 + l];
            y0 = fmaf(v, wy[d],        y0);
            y1 = fmaf(v, wy[128 + d],  y1);
        }
        float z0 = bz[0], z1 = bz[1];
#pragma unroll 4
        for (int cc = 0; cc < 256; cc++) {
            const float v = Q2[((size_t)cc * GR + g) * 127 + l];
            z0 = fmaf(v, wz[cc],       z0);
            z1 = fmaf(v, wz[256 + cc], z1);
        }
        a0 = y0 * z0; a1 = y1 * z1;
    }
    s0[l] = a0; s1[l] = a1;
    __syncthreads();
    for (int st = 64; st > 0; st >>= 1) {
        if (l < st) { s0[l] += s0[l + st]; s1[l] += s1[l + st]; }
        __syncthreads();
    }
    if (l == 0) {
        out[g * 2 + 0] = s0[0] / 127.f;
        out[g * 2 + 1] = s1[0] / 127.f;
    }
}

// ---------------- host orchestration ----------------
extern "C" void kernel_launch(void* const* d_in, const int* in_sizes, int n_in,
                              void* d_out, int out_size)
{
    const float* x    = (const float*)d_in[0];
    const int*   ei   = (const int*)  d_in[1];
    const float* ew   = (const float*)d_in[2];
    const float* ggw  = (const float*)d_in[4];
    const float* wih  = (const float*)d_in[5];
    const float* whh  = (const float*)d_in[6];
    const float* bih  = (const float*)d_in[7];
    const float* bhh  = (const float*)d_in[8];
    const float* c1w  = (const float*)d_in[9];
    const float* c1b  = (const float*)d_in[10];
    const float* c2w  = (const float*)d_in[11];
    const float* c2b  = (const float*)d_in[12];
    const float* cc1w = (const float*)d_in[13];
    const float* cc1b = (const float*)d_in[14];
    const float* cc2w = (const float*)d_in[15];
    const float* cc2b = (const float*)d_in[16];
    const float* bn1g = (const float*)d_in[17];
    const float* bn1b = (const float*)d_in[18];
    const float* bn2g = (const float*)d_in[19];
    const float* bn2b = (const float*)d_in[20];
    const float* myw  = (const float*)d_in[21];
    const float* myb  = (const float*)d_in[22];
    const float* mzw  = (const float*)d_in[23];
    const float* mzb  = (const float*)d_in[24];
    float* out = (float*)d_out;

    float *H, *Msg, *AGG, *GX, *GH, *WT, *CAT, *T1, *U1, *T2, *U2, *P2, *Q2, *MEAN, *RSTD;
    __nv_bfloat16 *Hhi, *Hlo, *Ahi, *Alo, *WThi, *WTlo, *IHhi, *IHlo, *HHhi, *HHlo;
    __nv_bfloat16 *CAThi, *CATlo, *P1hi, *P1lo, *Q1hi, *Q1lo;
    __nv_bfloat16 *CW1hi, *CW1lo, *CW2hi, *CW2lo, *CC1hi, *CC1lo, *CC2hi, *CC2lo;
    cudaGetSymbolAddress((void**)&H,   g_H);
    cudaGetSymbolAddress((void**)&Msg, g_M);
    cudaGetSymbolAddress((void**)&AGG, g_AGG);
    cudaGetSymbolAddress((void**)&GX,  g_GX);
    cudaGetSymbolAddress((void**)&GH,  g_GH);
    cudaGetSymbolAddress((void**)&WT,  g_WT);
    cudaGetSymbolAddress((void**)&CAT, g_CAT);
    cudaGetSymbolAddress((void**)&T1,  g_T1);
    cudaGetSymbolAddress((void**)&U1,  g_U1);
    cudaGetSymbolAddress((void**)&T2,  g_T2);
    cudaGetSymbolAddress((void**)&U2,  g_U2);
    cudaGetSymbolAddress((void**)&P2,  g_P2);
    cudaGetSymbolAddress((void**)&Q2,  g_Q2);
    cudaGetSymbolAddress((void**)&MEAN, g_MEAN);
    cudaGetSymbolAddress((void**)&RSTD, g_RSTD);
    cudaGetSymbolAddress((void**)&Hhi, g_Hhi);
    cudaGetSymbolAddress((void**)&Hlo, g_Hlo);
    cudaGetSymbolAddress((void**)&Ahi, g_Ahi);
    cudaGetSymbolAddress((void**)&Alo, g_Alo);
    cudaGetSymbolAddress((void**)&WThi, g_WThi);
    cudaGetSymbolAddress((void**)&WTlo, g_WTlo);
    cudaGetSymbolAddress((void**)&IHhi, g_IHhi);
    cudaGetSymbolAddress((void**)&IHlo, g_IHlo);
    cudaGetSymbolAddress((void**)&HHhi, g_HHhi);
    cudaGetSymbolAddress((void**)&HHlo, g_HHlo);
    cudaGetSymbolAddress((void**)&CAThi, g_CAThi);
    cudaGetSymbolAddress((void**)&CATlo, g_CATlo);
    cudaGetSymbolAddress((void**)&P1hi, g_P1hi);
    cudaGetSymbolAddress((void**)&P1lo, g_P1lo);
    cudaGetSymbolAddress((void**)&Q1hi, g_Q1hi);
    cudaGetSymbolAddress((void**)&Q1lo, g_Q1lo);
    cudaGetSymbolAddress((void**)&CW1hi, g_CW1hi);
    cudaGetSymbolAddress((void**)&CW1lo, g_CW1lo);
    cudaGetSymbolAddress((void**)&CW2hi, g_CW2hi);
    cudaGetSymbolAddress((void**)&CW2lo, g_CW2lo);
    cudaGetSymbolAddress((void**)&CC1hi, g_CC1hi);
    cudaGetSymbolAddress((void**)&CC1lo, g_CC1lo);
    cudaGetSymbolAddress((void**)&CC2hi, g_CC2hi);
    cudaGetSymbolAddress((void**)&CC2lo, g_CC2lo);

    cudaFuncSetAttribute(gemm_mma, cudaFuncAttributeMaxDynamicSharedMemorySize, MMA_SMEM);
    cudaFuncSetAttribute(conv_mma, cudaFuncAttributeMaxDynamicSharedMemorySize, CONV_SMEM);

    const size_t ndbytes = (size_t)N_NODES * DIM * sizeof(float);

    // ---- preamble: h0 = x, weight prep ----
    cudaMemcpyAsync(H, x, ndbytes, cudaMemcpyDeviceToDevice);
    split_kernel<<<(N_NODES * DIM / 4) / 256, 256>>>(x, Hhi, Hlo, N_NODES * DIM / 4);
    transpose_w_kernel<<<(GSTEPS * DIM * DIM) / 256, 256>>>(ggw, WT);
    split_kernel<<<(GSTEPS * DIM * DIM / 4 + 255) / 256, 256>>>(WT,  WThi, WTlo, GSTEPS * DIM * DIM / 4);
    split_kernel<<<(384 * DIM / 4 + 255) / 256, 256>>>(wih, IHhi, IHlo, 384 * DIM / 4);
    split_kernel<<<(384 * DIM / 4 + 255) / 256, 256>>>(whh, HHhi, HHlo, 384 * DIM / 4);
    convw_prep<<<(3 * 128 * 128 + 255) / 256, 256>>>(c1w,  CW1hi, CW1lo, 128, 128, 3);
    convw_prep<<<(128 * 128 + 255) / 256, 256>>>(c2w,  CW2hi, CW2lo, 128, 128, 1);
    convw_prep<<<(3 * 256 * 256 + 255) / 256, 256>>>(cc1w, CC1hi, CC1lo, 256, 256, 3);
    convw_prep<<<(256 * 256 + 255) / 256, 256>>>(cc2w, CC2hi, CC2lo, 256, 256, 1);

    // ---- GGNN loop ----
    for (int s = 0; s < GSTEPS; s++) {
        gemm_mma<<<dim3(512, 1), 256, MMA_SMEM>>>(Hhi, Hlo, WThi + s * DIM * DIM, WTlo + s * DIM * DIM,
                                                  nullptr, Msg, 128);
        cudaMemsetAsync(AGG, 0, ndbytes);
        scatter_kernel<<<(NE * 32) / 256, 256>>>(Msg, ei, ew, AGG);
        split_kernel<<<(N_NODES * DIM / 4) / 256, 256>>>(AGG, Ahi, Alo, N_NODES * DIM / 4);
        gemm_mma<<<dim3(512, 3), 256, MMA_SMEM>>>(Hhi, Hlo, HHhi, HHlo, bhh, GH, 384);
        gemm_mma<<<dim3(512, 3), 256, MMA_SMEM>>>(Ahi, Alo, IHhi, IHlo, bih, GX, 384);
        gru_kernel<<<(N_NODES * 32) / 256, 256>>>(GX, GH, H, Hhi, Hlo);
    }

    // ---- CAT = [h^T ; x^T] channel-major, then split ----
    transpose_nd<<<dim3(N_NODES / 32, 4), dim3(32, 8)>>>(H, CAT);
    transpose_nd<<<dim3(N_NODES / 32, 4), dim3(32, 8)>>>(x, CAT + (size_t)128 * N_NODES);
    split_kernel<<<(256 * N_NODES / 4) / 256, 256>>>(CAT, CAThi, CATlo, 256 * N_NODES / 4);

    // ---- branch Y ----
    conv_mma<<<dim3(512, 1), 256, CONV_SMEM>>>(CW1hi, CW1lo, CAThi, CATlo, c1b, T1, 128, 128, 3, 65536);
    bnstats_mask<<<128, 256>>>(T1, MEAN, RSTD);
    pool_bf16<3, 2><<<(128 * GR * 254) / 256, 256>>>(T1, MEAN, RSTD, bn1g, bn1b, P1hi, P1lo, 512, 254, 128 * GR * 254);
    conv_mma<<<dim3(254, 1), 256, CONV_SMEM>>>(CW2hi, CW2lo, P1hi, P1lo, c2b, T2, 128, 128, 1, 32512);
    bnstats_kernel<<<128, 256>>>(T2, 32512, MEAN, RSTD);
    pool_f32<2, 2><<<(128 * GR * 127) / 256, 256>>>(T2, MEAN, RSTD, bn1g, bn1b, P2, 254, 127, 128 * GR * 127);

    // ---- branch Z ----
    conv_mma<<<dim3(512, 2), 256, CONV_SMEM>>>(CC1hi, CC1lo, CAThi, CATlo, cc1b, U1, 256, 256, 3, 65536);
    bnstats_mask<<<256, 256>>>(U1, MEAN, RSTD);
    pool_bf16<3, 2><<<(256 * GR * 254) / 256, 256>>>(U1, MEAN, RSTD, bn2g, bn2b, Q1hi, Q1lo, 512, 254, 256 * GR * 254);
    conv_mma<<<dim3(254, 2), 256, CONV_SMEM>>>(CC2hi, CC2lo, Q1hi, Q1lo, cc2b, U2, 256, 256, 1, 32512);
    bnstats_kernel<<<256, 256>>>(U2, 32512, MEAN, RSTD);
    pool_f32<2, 2><<<(256 * GR * 127) / 256, 256>>>(U2, MEAN, RSTD, bn2g, bn2b, Q2, 254, 127, 256 * GR * 127);

    final_kernel<<<GR, 128>>>(P2, Q2, myw, myb, mzw, mzb, out);
}